// round 1
// baseline (speedup 1.0000x reference)
#include <cuda_runtime.h>
#include <cstdint>

#define NCEN   512
#define NKEYS  262144          // 512*512
#define EC1    130817          // E_COARSE + 1
#define NN     100000
#define EE     800000
#define HH     128

// output offsets (float elements)
#define O_NODE  0
#define O_ATTR  131072
#define O_EDGES 33620224
#define O_CCI   33881858
#define O_DIST  33981858

// ---------------- device scratch (no allocations allowed) ----------------
__device__ int g_cnt_key[NKEYS];
__device__ int g_slot_of_key[NKEYS];
__device__ int g_edge_off[NKEYS];
__device__ int g_cursor[NKEYS];
__device__ int g_key[EE];
__device__ int g_edge_sorted[EE];
__device__ int g_blk_occ[512];
__device__ int g_blk_cnt[512];
__device__ int g_cnt_node[NCEN];

// ---------------- helpers ----------------
__device__ __forceinline__ void fma2(unsigned long long &acc,
                                     unsigned long long a,
                                     unsigned long long b) {
    asm("fma.rn.f32x2 %0, %1, %2, %0;" : "+l"(acc) : "l"(a), "l"(b));
}
__device__ __forceinline__ float2 unpack2(unsigned long long v) {
    float2 r;
    asm("mov.b64 {%0, %1}, %2;" : "=f"(r.x), "=f"(r.y) : "l"(v));
    return r;
}

// ---------------- zero scratch ----------------
__global__ void k_zero() {
    int i = blockIdx.x * blockDim.x + threadIdx.x;
    if (i < NKEYS) g_cnt_key[i] = 0;
    if (i < NCEN)  g_cnt_node[i] = 0;
}

// ---------------- passthroughs + coarse_edges fill(-1) ----------------
__global__ void k_aux(const int* __restrict__ cci, const float* __restrict__ dist,
                      float* __restrict__ out) {
    int i = blockIdx.x * blockDim.x + threadIdx.x;
    if (i < 2 * EC1) out[O_EDGES + i] = -1.0f;
    if (i < NN) {
        out[O_CCI + i]  = (float)cci[i];
        out[O_DIST + i] = dist[i];
    }
}

// ---------------- edge keys + per-key counts ----------------
__global__ void k_edgekey(const int* __restrict__ ei, const int* __restrict__ cci) {
    int e = blockIdx.x * blockDim.x + threadIdx.x;
    if (e >= EE) return;
    int s = cci[ei[e]];
    int t = cci[ei[EE + e]];
    if (s == t) { g_key[e] = -1; return; }
    int a = min(s, t), b = max(s, t);
    int key = a * NCEN + b;
    g_key[e] = key;
    atomicAdd(&g_cnt_key[key], 1);
}

// ---------------- scan: pass1 block sums ----------------
__global__ void k_scan1() {
    __shared__ int so[512], sc[512];
    int t = threadIdx.x;
    int cnt = g_cnt_key[blockIdx.x * 512 + t];
    so[t] = (cnt > 0); sc[t] = cnt;
    __syncthreads();
    for (int s = 256; s > 0; s >>= 1) {
        if (t < s) { so[t] += so[t + s]; sc[t] += sc[t + s]; }
        __syncthreads();
    }
    if (t == 0) { g_blk_occ[blockIdx.x] = so[0]; g_blk_cnt[blockIdx.x] = sc[0]; }
}

// ---------------- scan: pass2 exclusive scan of 512 block sums ----------------
__global__ void k_scan2() {
    __shared__ int so[512], sc[512];
    int t = threadIdx.x;
    so[t] = g_blk_occ[t]; sc[t] = g_blk_cnt[t];
    __syncthreads();
    int own_o = so[t], own_c = sc[t];
    for (int off = 1; off < 512; off <<= 1) {
        int vo = (t >= off) ? so[t - off] : 0;
        int vc = (t >= off) ? sc[t - off] : 0;
        __syncthreads();
        so[t] += vo; sc[t] += vc;
        __syncthreads();
    }
    g_blk_occ[t] = so[t] - own_o;   // exclusive
    g_blk_cnt[t] = sc[t] - own_c;
}

// ---------------- scan: pass3 per-key slots/offsets + coarse_edges write ----------------
__global__ void k_scan3(float* __restrict__ out) {
    __shared__ int so[512], sc[512];
    int t = threadIdx.x;
    int key = blockIdx.x * 512 + t;
    int cnt = g_cnt_key[key];
    int occ = (cnt > 0);
    so[t] = occ; sc[t] = cnt;
    __syncthreads();
    for (int off = 1; off < 512; off <<= 1) {
        int vo = (t >= off) ? so[t - off] : 0;
        int vc = (t >= off) ? sc[t - off] : 0;
        __syncthreads();
        so[t] += vo; sc[t] += vc;
        __syncthreads();
    }
    int occ_ex = so[t] - occ + g_blk_occ[blockIdx.x];
    int cnt_ex = sc[t] - cnt + g_blk_cnt[blockIdx.x];
    g_slot_of_key[key] = occ_ex;
    g_edge_off[key]    = cnt_ex;
    g_cursor[key]      = cnt_ex;
    if (occ) {
        out[O_EDGES + occ_ex]       = (float)(key >> 9);
        out[O_EDGES + EC1 + occ_ex] = (float)(key & 511);
    }
}

// ---------------- counting-sort scatter ----------------
__global__ void k_sort() {
    int e = blockIdx.x * blockDim.x + threadIdx.x;
    if (e >= EE) return;
    int key = g_key[e];
    if (key < 0) return;
    int pos = atomicAdd(&g_cursor[key], 1);
    g_edge_sorted[pos] = e;
}

// ---------------- per-key edge-attr mean (warp per key) ----------------
__global__ void k_acc(const float* __restrict__ ea, float* __restrict__ out) {
    int warp = (blockIdx.x * blockDim.x + threadIdx.x) >> 5;
    int lane = threadIdx.x & 31;
    if (warp >= NKEYS) return;
    int cnt = g_cnt_key[warp];
    if (cnt == 0) return;
    int slot = g_slot_of_key[warp];
    int off  = g_edge_off[warp];
    const float4* ea4 = (const float4*)ea;
    float4 s0 = make_float4(0.f, 0.f, 0.f, 0.f);
    float4 s1 = make_float4(0.f, 0.f, 0.f, 0.f);
    for (int i = 0; i < cnt; i++) {
        int e = g_edge_sorted[off + i];
        float4 v0 = __ldg(&ea4[(size_t)e * 32 + lane]);
        float4 v1 = __ldg(&ea4[((size_t)EE + e) * 32 + lane]);
        s0.x += v0.x; s0.y += v0.y; s0.z += v0.z; s0.w += v0.w;
        s1.x += v1.x; s1.y += v1.y; s1.z += v1.z; s1.w += v1.w;
    }
    float inv = 1.0f / (float)cnt;
    float4* o = (float4*)(out + O_ATTR);
    o[(size_t)slot * 32 + lane] =
        make_float4(s0.x * inv, s0.y * inv, s0.z * inv, s0.w * inv);
    o[((size_t)EC1 + slot) * 32 + lane] =
        make_float4(s1.x * inv, s1.y * inv, s1.z * inv, s1.w * inv);
}

// ---------------- fused MLP + node pooling ----------------
#define TILE_N 32
#define WS_LD  132
#define TILES_PER_B 3125                 // 100000 / 32
__global__ __launch_bounds__(256, 2)
void k_mlp(const float* __restrict__ x, const float* __restrict__ dist,
           const float* __restrict__ W, const float* __restrict__ bias,
           const int* __restrict__ cci, float* __restrict__ out) {
    extern __shared__ float sm[];
    float* Ws = sm;                       // 128 cols x 132 (k = 0..128)
    float* xs = sm + 128 * WS_LD;         // 32 nodes x 132
    float* bs = xs + TILE_N * WS_LD;      // 128
    int t = threadIdx.x;

    // transpose W[129][128] -> Ws[j][k]
    for (int idx = t; idx < 129 * 128; idx += 256) {
        int k = idx >> 7, j = idx & 127;
        Ws[j * WS_LD + k] = W[idx];
    }
    if (t < 128) bs[t] = bias[t];
    __syncthreads();

    int tc = t & 31, tn = t >> 5;
    int colb  = tc * 4;
    int nodeb = tn * 4;

    float w128[4], bl[4];
#pragma unroll
    for (int c = 0; c < 4; c++) {
        w128[c] = Ws[(colb + c) * WS_LD + 128];
        bl[c]   = bs[colb + c];
    }

    const int totTiles = 2 * TILES_PER_B;
    for (int tile = blockIdx.x; tile < totTiles; tile += gridDim.x) {
        int b  = tile / TILES_PER_B;
        int n0 = (tile - b * TILES_PER_B) * TILE_N;
        __syncthreads();
        // load 32-node x tile (zero-padded)
#pragma unroll
        for (int r = 0; r < 4; r++) {
            int idx = r * 256 + t;
            int node = idx >> 5, q = idx & 31;
            int n = n0 + node;
            float4 v = make_float4(0.f, 0.f, 0.f, 0.f);
            if (n < NN) v = *(const float4*)&x[((size_t)b * NN + n) * HH + q * 4];
            *(float4*)&xs[node * WS_LD + q * 4] = v;
        }
        if (t < TILE_N) {
            int n = n0 + t;
            xs[t * WS_LD + 128] = (n < NN) ? dist[n] : 0.0f;
        }
        __syncthreads();

        unsigned long long acc[4][4];
#pragma unroll
        for (int i = 0; i < 4; i++)
#pragma unroll
            for (int c = 0; c < 4; c++) acc[i][c] = 0ull;

#pragma unroll 4
        for (int k = 0; k < 128; k += 4) {
            ulonglong2 xv[4], wv[4];
#pragma unroll
            for (int i = 0; i < 4; i++)
                xv[i] = *(const ulonglong2*)&xs[(nodeb + i) * WS_LD + k];
#pragma unroll
            for (int c = 0; c < 4; c++)
                wv[c] = *(const ulonglong2*)&Ws[(colb + c) * WS_LD + k];
#pragma unroll
            for (int i = 0; i < 4; i++)
#pragma unroll
                for (int c = 0; c < 4; c++) {
                    fma2(acc[i][c], xv[i].x, wv[c].x);
                    fma2(acc[i][c], xv[i].y, wv[c].y);
                }
        }

        // epilogue: relu + atomic segment-sum into node_avg region
#pragma unroll
        for (int i = 0; i < 4; i++) {
            int n = n0 + nodeb + i;
            if (n >= NN) continue;
            float d = xs[(nodeb + i) * WS_LD + 128];
            int cc = cci[n];
            float* ob = out + ((size_t)b * NCEN + cc) * HH;
#pragma unroll
            for (int c = 0; c < 4; c++) {
                float2 p = unpack2(acc[i][c]);
                float v = p.x + p.y + d * w128[c] + bl[c];
                v = fmaxf(v, 0.0f);
                atomicAdd(&ob[colb + c], v);
            }
        }
    }
}

// ---------------- centroid counts + mean divide ----------------
__global__ void k_hist(const int* __restrict__ cci) {
    int n = blockIdx.x * blockDim.x + threadIdx.x;
    if (n < NN) atomicAdd(&g_cnt_node[cci[n]], 1);
}
__global__ void k_div(float* __restrict__ out) {
    int i = blockIdx.x * blockDim.x + threadIdx.x;
    if (i >= 2 * NCEN * HH) return;
    int c = (i >> 7) & (NCEN - 1);
    int cnt = g_cnt_node[c];
    out[i] *= 1.0f / (float)max(cnt, 1);
}

// ---------------- launch ----------------
extern "C" void kernel_launch(void* const* d_in, const int* in_sizes, int n_in,
                              void* d_out, int out_size) {
    const float* x    = (const float*)d_in[0];
    const int*   ei   = (const int*)d_in[1];
    const float* ea   = (const float*)d_in[2];
    const int*   cci  = (const int*)d_in[4];
    const float* dist = (const float*)d_in[5];
    const float* W    = (const float*)d_in[6];
    const float* bias = (const float*)d_in[7];
    float* out = (float*)d_out;

    const int smem = (128 * WS_LD + TILE_N * WS_LD + 128) * 4;   // 84992 B
    cudaFuncSetAttribute(k_mlp, cudaFuncAttributeMaxDynamicSharedMemorySize, smem);

    // zero node_avg + coarse_edge_attrs regions (contiguous)
    cudaMemsetAsync(d_out, 0, (size_t)O_EDGES * 4);
    k_zero<<<1024, 256>>>();
    k_aux<<<1023, 256>>>(cci, dist, out);

    // edge pipeline
    k_edgekey<<<3125, 256>>>(ei, cci);
    k_scan1<<<512, 512>>>();
    k_scan2<<<1, 512>>>();
    k_scan3<<<512, 512>>>(out);
    k_sort<<<3125, 256>>>();
    k_acc<<<32768, 256>>>(ea, out);

    // node pipeline
    k_mlp<<<296, 256, smem>>>(x, dist, W, bias, cci, out);
    k_hist<<<391, 256>>>(cci);
    k_div<<<512, 256>>>(out);
}

// round 2
// speedup vs baseline: 1.2247x; 1.2247x over previous
#include <cuda_runtime.h>
#include <cstdint>

#define NCEN   512
#define NKEYS  262144          // 512*512
#define EC1    130817          // E_COARSE + 1
#define NN     100000
#define EE     800000
#define HH     128

// output offsets (float elements)
#define O_NODE  0
#define O_ATTR  131072
#define O_EDGES 33620224
#define O_CCI   33881858
#define O_DIST  33981858

// ---------------- device scratch (no allocations allowed) ----------------
__device__ int g_cnt_key[NKEYS];
__device__ int g_slot_of_key[NKEYS];
__device__ int g_edge_off[NKEYS];
__device__ int g_cursor[NKEYS];
__device__ int g_key[EE];
__device__ int g_edge_sorted[EE];
__device__ int g_blk_occ[512];
__device__ int g_blk_cnt[512];
__device__ int g_cnt_node[NCEN];
__device__ int g_nuniq;

// ---------------- helpers ----------------
__device__ __forceinline__ void fma2(unsigned long long &acc,
                                     unsigned long long a,
                                     unsigned long long b) {
    asm("fma.rn.f32x2 %0, %1, %2, %0;" : "+l"(acc) : "l"(a), "l"(b));
}
__device__ __forceinline__ float2 unpack2(unsigned long long v) {
    float2 r;
    asm("mov.b64 {%0, %1}, %2;" : "=f"(r.x), "=f"(r.y) : "l"(v));
    return r;
}
__device__ __forceinline__ unsigned long long pack2(float a, float b) {
    unsigned long long p;
    asm("mov.b64 %0, {%1, %2};" : "=l"(p) : "f"(a), "f"(b));
    return p;
}

// ---------------- zero scratch ----------------
__global__ void k_zero() {
    int i = blockIdx.x * blockDim.x + threadIdx.x;
    if (i < NKEYS) g_cnt_key[i] = 0;
    if (i < NCEN)  g_cnt_node[i] = 0;
}

// ---------------- passthroughs + coarse_edges fill(-1) ----------------
__global__ void k_aux(const int* __restrict__ cci, const float* __restrict__ dist,
                      float* __restrict__ out) {
    int i = blockIdx.x * blockDim.x + threadIdx.x;
    if (i < 2 * EC1) out[O_EDGES + i] = -1.0f;
    if (i < NN) {
        out[O_CCI + i]  = (float)cci[i];
        out[O_DIST + i] = dist[i];
    }
}

// ---------------- edge keys + per-key counts ----------------
__global__ void k_edgekey(const int* __restrict__ ei, const int* __restrict__ cci) {
    int e = blockIdx.x * blockDim.x + threadIdx.x;
    if (e >= EE) return;
    int s = cci[ei[e]];
    int t = cci[ei[EE + e]];
    if (s == t) { g_key[e] = -1; return; }
    int a = min(s, t), b = max(s, t);
    int key = a * NCEN + b;
    g_key[e] = key;
    atomicAdd(&g_cnt_key[key], 1);
}

// ---------------- scan: pass1 block sums ----------------
__global__ void k_scan1() {
    __shared__ int so[512], sc[512];
    int t = threadIdx.x;
    int cnt = g_cnt_key[blockIdx.x * 512 + t];
    so[t] = (cnt > 0); sc[t] = cnt;
    __syncthreads();
    for (int s = 256; s > 0; s >>= 1) {
        if (t < s) { so[t] += so[t + s]; sc[t] += sc[t + s]; }
        __syncthreads();
    }
    if (t == 0) { g_blk_occ[blockIdx.x] = so[0]; g_blk_cnt[blockIdx.x] = sc[0]; }
}

// ---------------- scan: pass2 exclusive scan of 512 block sums ----------------
__global__ void k_scan2() {
    __shared__ int so[512], sc[512];
    int t = threadIdx.x;
    so[t] = g_blk_occ[t]; sc[t] = g_blk_cnt[t];
    __syncthreads();
    int own_o = so[t], own_c = sc[t];
    for (int off = 1; off < 512; off <<= 1) {
        int vo = (t >= off) ? so[t - off] : 0;
        int vc = (t >= off) ? sc[t - off] : 0;
        __syncthreads();
        so[t] += vo; sc[t] += vc;
        __syncthreads();
    }
    g_blk_occ[t] = so[t] - own_o;   // exclusive
    g_blk_cnt[t] = sc[t] - own_c;
    if (t == 511) g_nuniq = so[511];   // total occupied keys
}

// ---------------- scan: pass3 per-key slots/offsets + coarse_edges write ----------------
__global__ void k_scan3(float* __restrict__ out) {
    __shared__ int so[512], sc[512];
    int t = threadIdx.x;
    int key = blockIdx.x * 512 + t;
    int cnt = g_cnt_key[key];
    int occ = (cnt > 0);
    so[t] = occ; sc[t] = cnt;
    __syncthreads();
    for (int off = 1; off < 512; off <<= 1) {
        int vo = (t >= off) ? so[t - off] : 0;
        int vc = (t >= off) ? sc[t - off] : 0;
        __syncthreads();
        so[t] += vo; sc[t] += vc;
        __syncthreads();
    }
    int occ_ex = so[t] - occ + g_blk_occ[blockIdx.x];
    int cnt_ex = sc[t] - cnt + g_blk_cnt[blockIdx.x];
    g_slot_of_key[key] = occ_ex;
    g_edge_off[key]    = cnt_ex;
    g_cursor[key]      = cnt_ex;
    if (occ) {
        out[O_EDGES + occ_ex]       = (float)(key >> 9);
        out[O_EDGES + EC1 + occ_ex] = (float)(key & 511);
    }
}

// ---------------- zero only the unoccupied attr slots ----------------
__global__ void k_zero_pad(float* __restrict__ out) {
    int nu = g_nuniq;
    float4 z = make_float4(0.f, 0.f, 0.f, 0.f);
    float4* p = (float4*)(out + O_ATTR);
    int t = threadIdx.x;
    for (int slot = nu + blockIdx.x; slot < EC1; slot += gridDim.x) {
        if (t < 32) p[(size_t)slot * 32 + t] = z;
        else        p[((size_t)EC1 + slot) * 32 + (t - 32)] = z;
    }
}

// ---------------- counting-sort scatter ----------------
__global__ void k_sort() {
    int e = blockIdx.x * blockDim.x + threadIdx.x;
    if (e >= EE) return;
    int key = g_key[e];
    if (key < 0) return;
    int pos = atomicAdd(&g_cursor[key], 1);
    g_edge_sorted[pos] = e;
}

// ---------------- per-key edge-attr mean (warp per key) ----------------
__global__ void k_acc(const float* __restrict__ ea, float* __restrict__ out) {
    int warp = (blockIdx.x * blockDim.x + threadIdx.x) >> 5;
    int lane = threadIdx.x & 31;
    if (warp >= NKEYS) return;
    int cnt = g_cnt_key[warp];
    if (cnt == 0) return;
    int slot = g_slot_of_key[warp];
    int off  = g_edge_off[warp];
    const float4* ea4 = (const float4*)ea;
    float4 s0 = make_float4(0.f, 0.f, 0.f, 0.f);
    float4 s1 = make_float4(0.f, 0.f, 0.f, 0.f);
    for (int base = 0; base < cnt; base += 32) {
        int m = min(32, cnt - base);
        int e_l = (lane < m) ? g_edge_sorted[off + base + lane] : 0;
#pragma unroll 4
        for (int i = 0; i < m; i++) {
            int e = __shfl_sync(0xffffffffu, e_l, i);
            float4 v0 = __ldg(&ea4[(size_t)e * 32 + lane]);
            float4 v1 = __ldg(&ea4[((size_t)EE + e) * 32 + lane]);
            s0.x += v0.x; s0.y += v0.y; s0.z += v0.z; s0.w += v0.w;
            s1.x += v1.x; s1.y += v1.y; s1.z += v1.z; s1.w += v1.w;
        }
    }
    float inv = 1.0f / (float)cnt;
    float4* o = (float4*)(out + O_ATTR);
    o[(size_t)slot * 32 + lane] =
        make_float4(s0.x * inv, s0.y * inv, s0.z * inv, s0.w * inv);
    o[((size_t)EC1 + slot) * 32 + lane] =
        make_float4(s1.x * inv, s1.y * inv, s1.z * inv, s1.w * inv);
}

// ---------------- fused MLP + node pooling (conflict-free) ----------------
// smem: Wp[64][128] ull pairs (W[2kp][j], W[2kp+1][j])  = 65536 B
//       xs[64][132] floats (node-major, [128]=distance) = 33792 B
#define TILE_N 64
#define XS_LD  132
#define TILES_PER_B 1563                 // ceil(100000 / 64)
#define MLP_SMEM (65536 + TILE_N * XS_LD * 4)
__global__ __launch_bounds__(256, 2)
void k_mlp(const float* __restrict__ x, const float* __restrict__ dist,
           const float* __restrict__ W, const float* __restrict__ bias,
           const int* __restrict__ cci, float* __restrict__ out) {
    extern __shared__ char smraw[];
    unsigned long long* Wp = (unsigned long long*)smraw;       // 8192 entries
    float* xs = (float*)(smraw + 65536);                       // 64*132 floats
    int t = threadIdx.x;

    // pair-transpose W[0:128][j] -> Wp[kp][j]
    for (int idx = t; idx < 64 * 128; idx += 256) {
        int kp = idx >> 7, j = idx & 127;
        float a = W[(2 * kp) * HH + j];
        float b = W[(2 * kp + 1) * HH + j];
        Wp[idx] = pack2(a, b);
    }

    int tc = t & 31, tn = t >> 5;
    int colb  = tc * 4;      // 4 columns per lane
    int nodeb = tn * 8;      // 8 nodes per warp

    float w128[4], bl[4];
#pragma unroll
    for (int c = 0; c < 4; c++) {
        w128[c] = __ldg(&W[128 * HH + colb + c]);
        bl[c]   = __ldg(&bias[colb + c]);
    }
    __syncthreads();

    const int totTiles = 2 * TILES_PER_B;
    for (int tile = blockIdx.x; tile < totTiles; tile += gridDim.x) {
        int b  = tile / TILES_PER_B;
        int n0 = (tile - b * TILES_PER_B) * TILE_N;
        __syncthreads();
        // load 64-node x tile (zero-padded), conflict-free stores
#pragma unroll
        for (int r = 0; r < 8; r++) {
            int idx = r * 256 + t;
            int node = idx >> 5, q = idx & 31;
            int n = n0 + node;
            float4 v = make_float4(0.f, 0.f, 0.f, 0.f);
            if (n < NN) v = *(const float4*)&x[((size_t)b * NN + n) * HH + q * 4];
            *(float4*)&xs[node * XS_LD + q * 4] = v;
        }
        if (t < TILE_N) {
            int n = n0 + t;
            xs[t * XS_LD + 128] = (n < NN) ? dist[n] : 0.0f;
        }
        __syncthreads();

        unsigned long long acc[8][4];
#pragma unroll
        for (int i = 0; i < 8; i++)
#pragma unroll
            for (int c = 0; c < 4; c++) acc[i][c] = 0ull;

#pragma unroll 2
        for (int kp = 0; kp < 64; kp++) {
            // W pairs for this thread's 4 columns: 32 contiguous bytes
            ulonglong2 w01 = *(const ulonglong2*)&Wp[kp * 128 + colb];
            ulonglong2 w23 = *(const ulonglong2*)&Wp[kp * 128 + colb + 2];
#pragma unroll
            for (int i = 0; i < 8; i++) {
                unsigned long long x2 =
                    *(const unsigned long long*)&xs[(nodeb + i) * XS_LD + 2 * kp];
                fma2(acc[i][0], x2, w01.x);
                fma2(acc[i][1], x2, w01.y);
                fma2(acc[i][2], x2, w23.x);
                fma2(acc[i][3], x2, w23.y);
            }
        }

        // epilogue: relu + atomic segment-sum into node_avg region
#pragma unroll
        for (int i = 0; i < 8; i++) {
            int n = n0 + nodeb + i;
            if (n >= NN) continue;
            float d = xs[(nodeb + i) * XS_LD + 128];
            int cc = cci[n];
            float* ob = out + ((size_t)b * NCEN + cc) * HH;
#pragma unroll
            for (int c = 0; c < 4; c++) {
                float2 p = unpack2(acc[i][c]);
                float v = p.x + p.y + d * w128[c] + bl[c];
                v = fmaxf(v, 0.0f);
                atomicAdd(&ob[colb + c], v);
            }
        }
    }
}

// ---------------- centroid counts + mean divide ----------------
__global__ void k_hist(const int* __restrict__ cci) {
    int n = blockIdx.x * blockDim.x + threadIdx.x;
    if (n < NN) atomicAdd(&g_cnt_node[cci[n]], 1);
}
__global__ void k_div(float* __restrict__ out) {
    int i = blockIdx.x * blockDim.x + threadIdx.x;
    if (i >= 2 * NCEN * HH) return;
    int c = (i >> 7) & (NCEN - 1);
    int cnt = g_cnt_node[c];
    out[i] *= 1.0f / (float)max(cnt, 1);
}

// ---------------- launch ----------------
extern "C" void kernel_launch(void* const* d_in, const int* in_sizes, int n_in,
                              void* d_out, int out_size) {
    const float* x    = (const float*)d_in[0];
    const int*   ei   = (const int*)d_in[1];
    const float* ea   = (const float*)d_in[2];
    const int*   cci  = (const int*)d_in[4];
    const float* dist = (const float*)d_in[5];
    const float* W    = (const float*)d_in[6];
    const float* bias = (const float*)d_in[7];
    float* out = (float*)d_out;

    cudaFuncSetAttribute(k_mlp, cudaFuncAttributeMaxDynamicSharedMemorySize, MLP_SMEM);

    // zero only the node_avg region (attr region handled by k_acc + k_zero_pad)
    cudaMemsetAsync(d_out, 0, (size_t)O_ATTR * 4);
    k_zero<<<1024, 256>>>();
    k_aux<<<1023, 256>>>(cci, dist, out);

    // edge pipeline
    k_edgekey<<<3125, 256>>>(ei, cci);
    k_scan1<<<512, 512>>>();
    k_scan2<<<1, 512>>>();
    k_scan3<<<512, 512>>>(out);
    k_zero_pad<<<2048, 64>>>(out);
    k_sort<<<3125, 256>>>();
    k_acc<<<32768, 256>>>(ea, out);

    // node pipeline
    k_mlp<<<296, 256, MLP_SMEM>>>(x, dist, W, bias, cci, out);
    k_hist<<<391, 256>>>(cci);
    k_div<<<512, 256>>>(out);
}

// round 4
// speedup vs baseline: 1.4171x; 1.1571x over previous
#include <cuda_runtime.h>
#include <cstdint>

#define NCEN   512
#define NKEYS  262144          // 512*512
#define EC1    130817          // E_COARSE + 1
#define NN     100000
#define EE     800000
#define HH     128

// output offsets (float elements)
#define O_NODE  0
#define O_ATTR  131072
#define O_EDGES 33620224
#define O_CCI   33881858
#define O_DIST  33981858

// ---------------- device scratch (no allocations allowed) ----------------
__device__ int g_cnt_key[NKEYS];
__device__ int g_slot_of_key[NKEYS];
__device__ int g_edge_off[NKEYS];
__device__ int g_cursor[NKEYS];
__device__ int g_key[EE];
__device__ int g_edge_sorted[EE];
__device__ int g_blk_occ[512];
__device__ int g_blk_cnt[512];
__device__ int g_cnt_node[NCEN];
__device__ int g_nuniq;

// ---------------- helpers ----------------
__device__ __forceinline__ void fma2(unsigned long long &acc,
                                     unsigned long long a,
                                     unsigned long long b) {
    asm("fma.rn.f32x2 %0, %1, %2, %0;" : "+l"(acc) : "l"(a), "l"(b));
}
__device__ __forceinline__ float2 unpack2(unsigned long long v) {
    float2 r;
    asm("mov.b64 {%0, %1}, %2;" : "=f"(r.x), "=f"(r.y) : "l"(v));
    return r;
}
__device__ __forceinline__ unsigned long long pack2(float a, float b) {
    unsigned long long p;
    asm("mov.b64 %0, {%1, %2};" : "=l"(p) : "f"(a), "f"(b));
    return p;
}

// ---------------- init: zero node region + scratch, aux copies, edge fill ----
__global__ void k_init(const int* __restrict__ cci, const float* __restrict__ dist,
                       float* __restrict__ out) {
    int i = blockIdx.x * blockDim.x + threadIdx.x;   // up to 524288
    out[O_NODE + i] = 0.0f;                          // node_avg region (2*512*128)
    if (i < NKEYS) g_cnt_key[i] = 0;
    if (i < NCEN)  g_cnt_node[i] = 0;
    if (i < 2 * EC1) out[O_EDGES + i] = -1.0f;
    if (i < NN) {
        out[O_CCI + i]  = (float)cci[i];
        out[O_DIST + i] = dist[i];
    }
}

// ---------------- edge keys + per-key counts + node histogram ----------------
__global__ void k_edgekey(const int* __restrict__ ei, const int* __restrict__ cci) {
    int e = blockIdx.x * blockDim.x + threadIdx.x;
    if (e < NN) atomicAdd(&g_cnt_node[cci[e]], 1);   // folded node histogram
    if (e >= EE) return;
    int s = cci[ei[e]];
    int t = cci[ei[EE + e]];
    if (s == t) { g_key[e] = -1; return; }
    int a = min(s, t), b = max(s, t);
    int key = a * NCEN + b;
    g_key[e] = key;
    atomicAdd(&g_cnt_key[key], 1);
}

// ---------------- scan: pass1 block sums ----------------
__global__ void k_scan1() {
    __shared__ int so[512], sc[512];
    int t = threadIdx.x;
    int cnt = g_cnt_key[blockIdx.x * 512 + t];
    so[t] = (cnt > 0); sc[t] = cnt;
    __syncthreads();
    for (int s = 256; s > 0; s >>= 1) {
        if (t < s) { so[t] += so[t + s]; sc[t] += sc[t + s]; }
        __syncthreads();
    }
    if (t == 0) { g_blk_occ[blockIdx.x] = so[0]; g_blk_cnt[blockIdx.x] = sc[0]; }
}

// ---------------- scan: pass2 exclusive scan of 512 block sums ----------------
__global__ void k_scan2() {
    __shared__ int so[512], sc[512];
    int t = threadIdx.x;
    so[t] = g_blk_occ[t]; sc[t] = g_blk_cnt[t];
    __syncthreads();
    int own_o = so[t], own_c = sc[t];
    for (int off = 1; off < 512; off <<= 1) {
        int vo = (t >= off) ? so[t - off] : 0;
        int vc = (t >= off) ? sc[t - off] : 0;
        __syncthreads();
        so[t] += vo; sc[t] += vc;
        __syncthreads();
    }
    g_blk_occ[t] = so[t] - own_o;   // exclusive
    g_blk_cnt[t] = sc[t] - own_c;
    if (t == 511) g_nuniq = so[511];
}

// ---------------- scan: pass3 per-key slots/offsets + coarse_edges write ------
__global__ void k_scan3(float* __restrict__ out) {
    __shared__ int so[512], sc[512];
    int t = threadIdx.x;
    int key = blockIdx.x * 512 + t;
    int cnt = g_cnt_key[key];
    int occ = (cnt > 0);
    so[t] = occ; sc[t] = cnt;
    __syncthreads();
    for (int off = 1; off < 512; off <<= 1) {
        int vo = (t >= off) ? so[t - off] : 0;
        int vc = (t >= off) ? sc[t - off] : 0;
        __syncthreads();
        so[t] += vo; sc[t] += vc;
        __syncthreads();
    }
    int occ_ex = so[t] - occ + g_blk_occ[blockIdx.x];
    int cnt_ex = sc[t] - cnt + g_blk_cnt[blockIdx.x];
    g_slot_of_key[key] = occ_ex;
    g_edge_off[key]    = cnt_ex;
    g_cursor[key]      = cnt_ex;
    if (occ) {
        out[O_EDGES + occ_ex]       = (float)(key >> 9);
        out[O_EDGES + EC1 + occ_ex] = (float)(key & 511);
    }
}

// ---------------- zero only the unoccupied attr slots ----------------
__global__ void k_zero_pad(float* __restrict__ out) {
    int nu = g_nuniq;
    float4 z = make_float4(0.f, 0.f, 0.f, 0.f);
    float4* p = (float4*)(out + O_ATTR);
    int t = threadIdx.x;
    for (int slot = nu + blockIdx.x; slot < EC1; slot += gridDim.x) {
        if (t < 32) p[(size_t)slot * 32 + t] = z;
        else        p[((size_t)EC1 + slot) * 32 + (t - 32)] = z;
    }
}

// ---------------- counting-sort scatter ----------------
__global__ void k_sort() {
    int e = blockIdx.x * blockDim.x + threadIdx.x;
    if (e >= EE) return;
    int key = g_key[e];
    if (key < 0) return;
    int pos = atomicAdd(&g_cursor[key], 1);
    g_edge_sorted[pos] = e;
}

// =====================================================================
// FUSED kernel: even blocks = MLP+pool (FMA-bound), odd blocks = edge
// attr mean (DRAM-bound). 296 blocks @ 99KB smem -> 2 CTAs/SM, one of
// each role per SM (statistically), overlapping compute with memory.
// =====================================================================
#define TILE_N 64
#define XS_LD  132
#define TILES_PER_B 1563                 // ceil(100000 / 64)
#define TOT_TILES (2 * TILES_PER_B)
#define MLP_SMEM (65536 + TILE_N * XS_LD * 4)
#define MLP_BLOCKS 148
#define ACC_BLOCKS 148

__global__ __launch_bounds__(256, 2)
void k_fused(const float* __restrict__ x, const float* __restrict__ dist,
             const float* __restrict__ W, const float* __restrict__ bias,
             const int* __restrict__ cci, const float* __restrict__ ea,
             float* __restrict__ out) {
    int role = blockIdx.x & 1;
    int gidx = blockIdx.x >> 1;
    int t = threadIdx.x;

    if (role == 1) {
        // ---------------- edge-attr mean role (persistent warps) ----------------
        int wid  = t >> 5;
        int lane = t & 31;
        int warp = gidx * 8 + wid;                    // 0 .. 1183
        const float4* ea4 = (const float4*)ea;
        float4* o = (float4*)(out + O_ATTR);
        for (int key = warp; key < NKEYS; key += ACC_BLOCKS * 8) {
            int cnt = g_cnt_key[key];
            if (cnt == 0) continue;
            int slot = g_slot_of_key[key];
            int off  = g_edge_off[key];
            float4 s0 = make_float4(0.f, 0.f, 0.f, 0.f);
            float4 s1 = make_float4(0.f, 0.f, 0.f, 0.f);
            for (int base = 0; base < cnt; base += 32) {
                int m = min(32, cnt - base);
                int e_l = (lane < m) ? g_edge_sorted[off + base + lane] : 0;
#pragma unroll 4
                for (int i = 0; i < m; i++) {
                    int e = __shfl_sync(0xffffffffu, e_l, i);
                    float4 v0 = __ldg(&ea4[(size_t)e * 32 + lane]);
                    float4 v1 = __ldg(&ea4[((size_t)EE + e) * 32 + lane]);
                    s0.x += v0.x; s0.y += v0.y; s0.z += v0.z; s0.w += v0.w;
                    s1.x += v1.x; s1.y += v1.y; s1.z += v1.z; s1.w += v1.w;
                }
            }
            float inv = 1.0f / (float)cnt;
            o[(size_t)slot * 32 + lane] =
                make_float4(s0.x * inv, s0.y * inv, s0.z * inv, s0.w * inv);
            o[((size_t)EC1 + slot) * 32 + lane] =
                make_float4(s1.x * inv, s1.y * inv, s1.z * inv, s1.w * inv);
        }
        return;
    }

    // ---------------- MLP + pooling role ----------------
    extern __shared__ char smraw[];
    unsigned long long* Wp = (unsigned long long*)smraw;       // 64x128 pairs
    float* xs = (float*)(smraw + 65536);                       // 64*132 floats

    // pair-transpose W[0:128][j] -> Wp[kp][j]
    for (int idx = t; idx < 64 * 128; idx += 256) {
        int kp = idx >> 7, j = idx & 127;
        float a = W[(2 * kp) * HH + j];
        float b = W[(2 * kp + 1) * HH + j];
        Wp[idx] = pack2(a, b);
    }

    int tc = t & 31, tn = t >> 5;
    int colb  = tc * 4;      // 4 columns per lane
    int nodeb = tn * 8;      // 8 nodes per warp

    float w128[4], bl[4];
#pragma unroll
    for (int c = 0; c < 4; c++) {
        w128[c] = __ldg(&W[128 * HH + colb + c]);
        bl[c]   = __ldg(&bias[colb + c]);
    }
    __syncthreads();

    for (int tile = gidx; tile < TOT_TILES; tile += MLP_BLOCKS) {
        int b  = tile / TILES_PER_B;
        int n0 = (tile - b * TILES_PER_B) * TILE_N;
        __syncthreads();
#pragma unroll
        for (int r = 0; r < 8; r++) {
            int idx = r * 256 + t;
            int node = idx >> 5, q = idx & 31;
            int n = n0 + node;
            float4 v = make_float4(0.f, 0.f, 0.f, 0.f);
            if (n < NN) v = *(const float4*)&x[((size_t)b * NN + n) * HH + q * 4];
            *(float4*)&xs[node * XS_LD + q * 4] = v;
        }
        if (t < TILE_N) {
            int n = n0 + t;
            xs[t * XS_LD + 128] = (n < NN) ? dist[n] : 0.0f;
        }
        __syncthreads();

        unsigned long long acc[8][4];
#pragma unroll
        for (int i = 0; i < 8; i++)
#pragma unroll
            for (int c = 0; c < 4; c++) acc[i][c] = 0ull;

#pragma unroll 2
        for (int kp = 0; kp < 64; kp++) {
            ulonglong2 w01 = *(const ulonglong2*)&Wp[kp * 128 + colb];
            ulonglong2 w23 = *(const ulonglong2*)&Wp[kp * 128 + colb + 2];
#pragma unroll
            for (int i = 0; i < 8; i++) {
                unsigned long long x2 =
                    *(const unsigned long long*)&xs[(nodeb + i) * XS_LD + 2 * kp];
                fma2(acc[i][0], x2, w01.x);
                fma2(acc[i][1], x2, w01.y);
                fma2(acc[i][2], x2, w23.x);
                fma2(acc[i][3], x2, w23.y);
            }
        }

        // epilogue: relu + atomic segment-sum into node_avg region (REDG)
#pragma unroll
        for (int i = 0; i < 8; i++) {
            int n = n0 + nodeb + i;
            if (n >= NN) continue;
            float d = xs[(nodeb + i) * XS_LD + 128];
            int cc = cci[n];
            float* ob = out + ((size_t)b * NCEN + cc) * HH;
#pragma unroll
            for (int c = 0; c < 4; c++) {
                float2 p = unpack2(acc[i][c]);
                float v = p.x + p.y + d * w128[c] + bl[c];
                v = fmaxf(v, 0.0f);
                atomicAdd(&ob[colb + c], v);
            }
        }
    }
}

// ---------------- node mean divide ----------------
__global__ void k_div(float* __restrict__ out) {
    int i = blockIdx.x * blockDim.x + threadIdx.x;
    if (i >= 2 * NCEN * HH) return;
    int c = (i >> 7) & (NCEN - 1);
    int cnt = g_cnt_node[c];
    out[i] *= 1.0f / (float)max(cnt, 1);
}

// ---------------- launch ----------------
extern "C" void kernel_launch(void* const* d_in, const int* in_sizes, int n_in,
                              void* d_out, int out_size) {
    const float* x    = (const float*)d_in[0];
    const int*   ei   = (const int*)d_in[1];
    const float* ea   = (const float*)d_in[2];
    const int*   cci  = (const int*)d_in[4];
    const float* dist = (const float*)d_in[5];
    const float* W    = (const float*)d_in[6];
    const float* bias = (const float*)d_in[7];
    float* out = (float*)d_out;

    cudaFuncSetAttribute(k_fused, cudaFuncAttributeMaxDynamicSharedMemorySize, MLP_SMEM);

    k_init<<<2048, 256>>>(cci, dist, out);          // 524288 threads
    k_edgekey<<<3125, 256>>>(ei, cci);
    k_scan1<<<512, 512>>>();
    k_scan2<<<1, 512>>>();
    k_scan3<<<512, 512>>>(out);
    k_zero_pad<<<2048, 64>>>(out);
    k_sort<<<3125, 256>>>();
    k_fused<<<MLP_BLOCKS + ACC_BLOCKS, 256, MLP_SMEM>>>(x, dist, W, bias, cci, ea, out);
    k_div<<<512, 256>>>(out);
}